// round 3
// baseline (speedup 1.0000x reference)
#include <cuda_runtime.h>
#include <cuda_bf16.h>

// ---------------------------------------------------------------------------
// Problem constants
// ---------------------------------------------------------------------------
#define BATCH 4
#define DMODEL 768
#define NHEAD 12
#define HDIM 64
#define NLVL 3
#define NPT 4
#define LQ 4096           // 64 x 64 query grid
#define LIN 16464         // 112*112 + 56*56 + 28*28

// ---------------------------------------------------------------------------
// Scratch (device globals; no runtime allocation allowed)
// ---------------------------------------------------------------------------
__device__ __nv_bfloat16 g_qln[(size_t)BATCH * LQ * DMODEL];        // 25 MB
__device__ __nv_bfloat16 g_fln[(size_t)BATCH * LIN * DMODEL];       // 101 MB
__device__ __nv_bfloat16 g_val[(size_t)BATCH * LIN * DMODEL];       // 101 MB
__device__ float         g_off[(size_t)BATCH * LQ * NHEAD * NLVL * NPT * 2];  // 19 MB
__device__ float         g_aw [(size_t)BATCH * LQ * NHEAD * NLVL * NPT];      // 9.4 MB
__device__ __nv_bfloat16 g_sam[(size_t)BATCH * LQ * DMODEL];        // 25 MB
__device__ __nv_bfloat16 g_Wval[DMODEL * DMODEL];
__device__ __nv_bfloat16 g_Wout[DMODEL * DMODEL];
__device__ __nv_bfloat16 g_Woff[DMODEL * NHEAD * NLVL * NPT * 2];
__device__ __nv_bfloat16 g_Wattn[DMODEL * NHEAD * NLVL * NPT];

// ---------------------------------------------------------------------------
// fp32 -> bf16 convert
// ---------------------------------------------------------------------------
__global__ void f2bf_kernel(const float* __restrict__ in, __nv_bfloat16* __restrict__ out, int n) {
    int i = blockIdx.x * 256 + threadIdx.x;
    if (i < n) out[i] = __float2bfloat16(in[i]);
}

// ---------------------------------------------------------------------------
// LayerNorm over last dim (768), one block per row, write bf16
// ---------------------------------------------------------------------------
__global__ void __launch_bounds__(256) ln_kernel(
    const float* __restrict__ x, const float* __restrict__ g,
    const float* __restrict__ b, __nv_bfloat16* __restrict__ out)
{
    int row = blockIdx.x;
    const float* xr = x + (size_t)row * DMODEL;
    float v[3];
    float s = 0.f, s2 = 0.f;
#pragma unroll
    for (int i = 0; i < 3; i++) {
        v[i] = xr[threadIdx.x + i * 256];
        s += v[i];
        s2 += v[i] * v[i];
    }
    __shared__ float red0[32], red1[32];
#pragma unroll
    for (int o = 16; o > 0; o >>= 1) {
        s  += __shfl_xor_sync(0xFFFFFFFFu, s,  o);
        s2 += __shfl_xor_sync(0xFFFFFFFFu, s2, o);
    }
    int wid = threadIdx.x >> 5, lid = threadIdx.x & 31;
    if (lid == 0) { red0[wid] = s; red1[wid] = s2; }
    __syncthreads();
    if (wid == 0) {
        s  = (lid < 8) ? red0[lid] : 0.f;
        s2 = (lid < 8) ? red1[lid] : 0.f;
#pragma unroll
        for (int o = 4; o > 0; o >>= 1) {
            s  += __shfl_xor_sync(0xFFFFFFFFu, s,  o);
            s2 += __shfl_xor_sync(0xFFFFFFFFu, s2, o);
        }
        if (lid == 0) { red0[0] = s; red1[0] = s2; }
    }
    __syncthreads();
    float mean = red0[0] * (1.f / DMODEL);
    float var  = red1[0] * (1.f / DMODEL) - mean * mean;
    float rstd = rsqrtf(var + 1e-6f);
    __nv_bfloat16* o = out + (size_t)row * DMODEL;
#pragma unroll
    for (int i = 0; i < 3; i++) {
        int c = threadIdx.x + i * 256;
        o[c] = __float2bfloat16((v[i] - mean) * rstd * g[c] + b[c]);
    }
}

// ---------------------------------------------------------------------------
// bf16-in fp32-accum SIMT GEMM: C[M,N] = A[M,768] @ W[768,N] + bias
// Tile 128x64x16, 256 threads, 8x4 per thread.
// EPI 0: float C;  EPI 1: bf16 C;  EPI 2: out = resid + gamma*(acc+bias)
// ---------------------------------------------------------------------------
template <int EPI>
__global__ void __launch_bounds__(256) gemm_kernel(
    const __nv_bfloat16* __restrict__ A, const __nv_bfloat16* __restrict__ W,
    const float* __restrict__ bias, int M, int N,
    float* __restrict__ Cf, __nv_bfloat16* __restrict__ Cbf,
    const float* __restrict__ resid, const float* __restrict__ gamma)
{
    __shared__ float As[16][132];
    __shared__ float Bs[16][64];
    const int tx = threadIdx.x & 15;
    const int ty = threadIdx.x >> 4;
    const int m0 = blockIdx.x * 128;
    const int n0 = blockIdx.y * 64;

    const int lr  = threadIdx.x >> 1;          // A: row within tile
    const int lh  = threadIdx.x & 1;           // A: k half (8 elems)
    const int bkr = threadIdx.x >> 4;          // B: k row
    const int bkc = (threadIdx.x & 15) * 4;    // B: col within tile

    float acc[8][4];
#pragma unroll
    for (int i = 0; i < 8; i++)
#pragma unroll
        for (int j = 0; j < 4; j++) acc[i][j] = 0.f;

    for (int k0 = 0; k0 < DMODEL; k0 += 16) {
        // Load A tile (128x16 bf16), transpose into As[k][m] as fp32
        {
            int gr = m0 + lr;
            uint4 raw = make_uint4(0u, 0u, 0u, 0u);
            if (gr < M)
                raw = *reinterpret_cast<const uint4*>(A + (size_t)gr * DMODEL + k0 + lh * 8);
            const __nv_bfloat162* p = reinterpret_cast<const __nv_bfloat162*>(&raw);
#pragma unroll
            for (int j = 0; j < 4; j++) {
                float2 f = __bfloat1622float2(p[j]);
                As[lh * 8 + 2 * j][lr]     = f.x;
                As[lh * 8 + 2 * j + 1][lr] = f.y;
            }
        }
        // Load B tile (16x64 bf16) as fp32
        {
            int gc = n0 + bkc;
            uint2 raw = make_uint2(0u, 0u);
            if (gc < N)
                raw = *reinterpret_cast<const uint2*>(W + (size_t)(k0 + bkr) * N + gc);
            const __nv_bfloat162* p = reinterpret_cast<const __nv_bfloat162*>(&raw);
#pragma unroll
            for (int j = 0; j < 2; j++) {
                float2 f = __bfloat1622float2(p[j]);
                Bs[bkr][bkc + 2 * j]     = f.x;
                Bs[bkr][bkc + 2 * j + 1] = f.y;
            }
        }
        __syncthreads();
#pragma unroll
        for (int k = 0; k < 16; k++) {
            float a[8], bb[4];
#pragma unroll
            for (int i = 0; i < 8; i++) a[i] = As[k][ty * 8 + i];
#pragma unroll
            for (int j = 0; j < 4; j++) bb[j] = Bs[k][tx * 4 + j];
#pragma unroll
            for (int i = 0; i < 8; i++)
#pragma unroll
                for (int j = 0; j < 4; j++) acc[i][j] += a[i] * bb[j];
        }
        __syncthreads();
    }

#pragma unroll
    for (int i = 0; i < 8; i++) {
        int m = m0 + ty * 8 + i;
        if (m >= M) continue;
#pragma unroll
        for (int j = 0; j < 4; j++) {
            int n = n0 + tx * 4 + j;
            if (n >= N) continue;
            float r = acc[i][j] + bias[n];
            if (EPI == 0) {
                Cf[(size_t)m * N + n] = r;
            } else if (EPI == 1) {
                Cbf[(size_t)m * N + n] = __float2bfloat16(r);
            } else {
                Cf[(size_t)m * DMODEL + n] =
                    resid[(size_t)m * DMODEL + n] + gamma[n] * r;
            }
        }
    }
}

// ---------------------------------------------------------------------------
// Softmax over groups of 12 (NL*NP), in place
// ---------------------------------------------------------------------------
__global__ void softmax12_kernel(float* __restrict__ aw, int ngroups) {
    int i = blockIdx.x * 256 + threadIdx.x;
    if (i >= ngroups) return;
    float* p = aw + (size_t)i * 12;
    float v[12];
    float m = -1e30f;
#pragma unroll
    for (int j = 0; j < 12; j++) { v[j] = p[j]; m = fmaxf(m, v[j]); }
    float s = 0.f;
#pragma unroll
    for (int j = 0; j < 12; j++) { v[j] = __expf(v[j] - m); s += v[j]; }
    float inv = 1.f / s;
#pragma unroll
    for (int j = 0; j < 12; j++) p[j] = v[j] * inv;
}

// ---------------------------------------------------------------------------
// Deformable sampling: one warp per (b, q, h). Each lane owns 2 of 64 dims.
// ---------------------------------------------------------------------------
__global__ void __launch_bounds__(256) sample_kernel(
    const float* __restrict__ off, const float* __restrict__ aw,
    const __nv_bfloat16* __restrict__ val, __nv_bfloat16* __restrict__ sam)
{
    // level tables live inside the kernel: fully unrolled -> immediates
    constexpr int lvl_h[3] = {112, 56, 28};
    constexpr int lvl_w[3] = {112, 56, 28};
    constexpr int lvl_s[3] = {0, 12544, 15680};

    int warp = (blockIdx.x * blockDim.x + threadIdx.x) >> 5;
    int lane = threadIdx.x & 31;
    if (warp >= BATCH * LQ * NHEAD) return;
    int h  = warp % NHEAD;
    int bq = warp / NHEAD;
    int q  = bq % LQ;
    int b  = bq / LQ;

    float rx = ((q & 63) + 0.5f) * (1.f / 64.f);
    float ry = ((q >> 6) + 0.5f) * (1.f / 64.f);

    const float* offp = off + (size_t)warp * (NLVL * NPT * 2);
    const float* awp  = aw  + (size_t)warp * (NLVL * NPT);

    float acc0 = 0.f, acc1 = 0.f;

#pragma unroll
    for (int l = 0; l < NLVL; l++) {
        const int h_ = lvl_h[l], w_ = lvl_w[l], st = lvl_s[l];
        const float invw = 1.f / (float)w_, invh = 1.f / (float)h_;
#pragma unroll
        for (int p = 0; p < NPT; p++) {
            float ox = offp[(l * NPT + p) * 2];
            float oy = offp[(l * NPT + p) * 2 + 1];
            float a  = awp[l * NPT + p];
            float x = (rx + ox * invw) * (float)w_ - 0.5f;
            float y = (ry + oy * invh) * (float)h_ - 0.5f;
            float x0f = floorf(x), y0f = floorf(y);
            float wx = x - x0f, wy = y - y0f;
            int x0 = (int)x0f, y0 = (int)y0f;
            float w00 = (1.f - wx) * (1.f - wy) * a;
            float w01 = wx * (1.f - wy) * a;
            float w10 = (1.f - wx) * wy * a;
            float w11 = wx * wy * a;

            const int xs[4] = {x0, x0 + 1, x0, x0 + 1};
            const int ys[4] = {y0, y0, y0 + 1, y0 + 1};
            const float ws[4] = {w00, w01, w10, w11};
#pragma unroll
            for (int c = 0; c < 4; c++) {
                int xi = xs[c], yi = ys[c];
                if (xi >= 0 && xi < w_ && yi >= 0 && yi < h_) {
                    size_t base = (((size_t)b * LIN + st + (size_t)yi * w_ + xi) * NHEAD + h)
                                  * HDIM + lane * 2;
                    __nv_bfloat162 v2 = *reinterpret_cast<const __nv_bfloat162*>(val + base);
                    float2 f = __bfloat1622float2(v2);
                    acc0 += ws[c] * f.x;
                    acc1 += ws[c] * f.y;
                }
            }
        }
    }

    size_t so = (size_t)(b * LQ + q) * DMODEL + h * HDIM + lane * 2;
    __nv_bfloat162 r;
    r.x = __float2bfloat16(acc0);
    r.y = __float2bfloat16(acc1);
    *reinterpret_cast<__nv_bfloat162*>(sam + so) = r;
}

// ---------------------------------------------------------------------------
// Launch
// ---------------------------------------------------------------------------
extern "C" void kernel_launch(void* const* d_in, const int* in_sizes, int n_in,
                              void* d_out, int out_size)
{
    const float* query  = (const float*)d_in[0];
    const float* feat   = (const float*)d_in[1];
    const float* ln_q_g = (const float*)d_in[2];
    const float* ln_q_b = (const float*)d_in[3];
    const float* ln_f_g = (const float*)d_in[4];
    const float* ln_f_b = (const float*)d_in[5];
    const float* W_off  = (const float*)d_in[6];
    const float* b_off  = (const float*)d_in[7];
    const float* W_attn = (const float*)d_in[8];
    const float* b_attn = (const float*)d_in[9];
    const float* W_val  = (const float*)d_in[10];
    const float* b_val  = (const float*)d_in[11];
    const float* W_out  = (const float*)d_in[12];
    const float* b_out  = (const float*)d_in[13];
    const float* gamma  = (const float*)d_in[14];
    float* out = (float*)d_out;

    __nv_bfloat16 *p_qln, *p_fln, *p_val, *p_sam, *p_Wval, *p_Wout, *p_Woff, *p_Wattn;
    float *p_off, *p_aw;
    cudaGetSymbolAddress((void**)&p_qln,  g_qln);
    cudaGetSymbolAddress((void**)&p_fln,  g_fln);
    cudaGetSymbolAddress((void**)&p_val,  g_val);
    cudaGetSymbolAddress((void**)&p_sam,  g_sam);
    cudaGetSymbolAddress((void**)&p_Wval, g_Wval);
    cudaGetSymbolAddress((void**)&p_Wout, g_Wout);
    cudaGetSymbolAddress((void**)&p_Woff, g_Woff);
    cudaGetSymbolAddress((void**)&p_Wattn,g_Wattn);
    cudaGetSymbolAddress((void**)&p_off,  g_off);
    cudaGetSymbolAddress((void**)&p_aw,   g_aw);

    const int NOFF  = NHEAD * NLVL * NPT * 2;   // 288
    const int NATT  = NHEAD * NLVL * NPT;       // 144
    const int Mq    = BATCH * LQ;               // 16384
    const int Mf    = BATCH * LIN;              // 65856

    // 1. weights -> bf16
    {
        int n = DMODEL * DMODEL;
        f2bf_kernel<<<(n + 255) / 256, 256>>>(W_val, p_Wval, n);
        f2bf_kernel<<<(n + 255) / 256, 256>>>(W_out, p_Wout, n);
        n = DMODEL * NOFF;
        f2bf_kernel<<<(n + 255) / 256, 256>>>(W_off, p_Woff, n);
        n = DMODEL * NATT;
        f2bf_kernel<<<(n + 255) / 256, 256>>>(W_attn, p_Wattn, n);
    }

    // 2. LayerNorms
    ln_kernel<<<Mf, 256>>>(feat, ln_f_g, ln_f_b, p_fln);
    ln_kernel<<<Mq, 256>>>(query, ln_q_g, ln_q_b, p_qln);

    // 3. value = ln(feat) @ W_val + b_val   (bf16 out)
    gemm_kernel<1><<<dim3((Mf + 127) / 128, DMODEL / 64), 256>>>(
        p_fln, p_Wval, b_val, Mf, DMODEL, nullptr, p_val, nullptr, nullptr);

    // 4. offsets = ln(q) @ W_off + b_off   (fp32 out)
    gemm_kernel<0><<<dim3(Mq / 128, (NOFF + 63) / 64), 256>>>(
        p_qln, p_Woff, b_off, Mq, NOFF, p_off, nullptr, nullptr, nullptr);

    // 5. attn logits = ln(q) @ W_attn + b_attn  (fp32 out)
    gemm_kernel<0><<<dim3(Mq / 128, (NATT + 63) / 64), 256>>>(
        p_qln, p_Wattn, b_attn, Mq, NATT, p_aw, nullptr, nullptr, nullptr);

    // 6. softmax over NL*NP=12
    softmax12_kernel<<<(Mq * NHEAD) / 256, 256>>>(p_aw, Mq * NHEAD);

    // 7. deformable sampling -> g_sam (bf16)
    {
        int warps = Mq * NHEAD;                 // 196608
        sample_kernel<<<warps / 8, 256>>>(p_off, p_aw, p_val, p_sam);
    }

    // 8. out = query + gamma * (g_sam @ W_out + b_out)
    gemm_kernel<2><<<dim3(Mq / 128, DMODEL / 64), 256>>>(
        p_sam, p_Wout, b_out, Mq, DMODEL, out, nullptr, query, gamma);
}

// round 6
// speedup vs baseline: 3.3910x; 3.3910x over previous
#include <cuda_runtime.h>
#include <cuda_bf16.h>
#include <cstdint>

// ---------------------------------------------------------------------------
// Problem constants
// ---------------------------------------------------------------------------
#define BATCH 4
#define DMODEL 768
#define NHEAD 12
#define HDIM 64
#define NLVL 3
#define NPT 4
#define LQ 4096           // 64 x 64 query grid
#define LIN 16464         // 112*112 + 56*56 + 28*28
#define NOFF 288          // NH*NL*NP*2
#define NATT 144          // NH*NL*NP
#define NCOMB 432         // NOFF+NATT
#define NCOMB_PAD 512

// GEMM tiling
#define BM 128
#define BN 128
#define BK 32
#define APAD 40            // bf16 elements per SMEM row (32 + 8 pad) = 80 bytes
#define KTILES (DMODEL / BK)   // 24

// ---------------------------------------------------------------------------
// Scratch (device globals; no runtime allocation allowed)
// ---------------------------------------------------------------------------
__device__ __nv_bfloat16 g_qln[(size_t)BATCH * LQ * DMODEL];
__device__ __nv_bfloat16 g_fln[(size_t)BATCH * LIN * DMODEL];
__device__ __nv_bfloat16 g_val[(size_t)BATCH * LIN * DMODEL];
__device__ float         g_off[(size_t)BATCH * LQ * NOFF];
__device__ float         g_aw [(size_t)BATCH * LQ * NATT];
__device__ __nv_bfloat16 g_sam[(size_t)BATCH * LQ * DMODEL];
__device__ __nv_bfloat16 g_WvalT[DMODEL * DMODEL];        // [n][k]
__device__ __nv_bfloat16 g_WoutT[DMODEL * DMODEL];        // [n][k]
__device__ __nv_bfloat16 g_WcombT[NCOMB_PAD * DMODEL];    // [n][k], rows >=432 zero

// ---------------------------------------------------------------------------
// helpers
// ---------------------------------------------------------------------------
__device__ __forceinline__ uint32_t smem_u32(const void* p) {
    uint32_t a;
    asm("{ .reg .u64 t; cvta.to.shared.u64 t, %1; cvt.u32.u64 %0, t; }" : "=r"(a) : "l"(p));
    return a;
}

#define CP_ASYNC16(sp, gp) \
    asm volatile("cp.async.cg.shared.global [%0], [%1], 16;" :: "r"(sp), "l"(gp) : "memory")
#define CP_COMMIT() asm volatile("cp.async.commit_group;" ::: "memory")
#define CP_WAIT1()  asm volatile("cp.async.wait_group 1;" ::: "memory")

#define LDSM_X4(r, addr)                                                      \
    asm volatile("ldmatrix.sync.aligned.m8n8.x4.shared.b16 {%0,%1,%2,%3}, [%4];" \
        : "=r"((r)[0]), "=r"((r)[1]), "=r"((r)[2]), "=r"((r)[3]) : "r"(addr))
#define LDSM_X2(r, addr)                                                      \
    asm volatile("ldmatrix.sync.aligned.m8n8.x2.shared.b16 {%0,%1}, [%2];"    \
        : "=r"((r)[0]), "=r"((r)[1]) : "r"(addr))

#define MMA_16816(c, a, b)                                                    \
    asm volatile("mma.sync.aligned.m16n8k16.row.col.f32.bf16.bf16.f32 "       \
        "{%0,%1,%2,%3}, {%4,%5,%6,%7}, {%8,%9}, {%0,%1,%2,%3};"               \
        : "+f"((c)[0]), "+f"((c)[1]), "+f"((c)[2]), "+f"((c)[3])              \
        : "r"((a)[0]), "r"((a)[1]), "r"((a)[2]), "r"((a)[3]),                 \
          "r"((b)[0]), "r"((b)[1]))

// ---------------------------------------------------------------------------
// Weight transpose kernels (fp32 [K,N] -> bf16 [N,K])
// ---------------------------------------------------------------------------
__global__ void wtrans_kernel(const float* __restrict__ W, __nv_bfloat16* __restrict__ Wt, int N) {
    int idx = blockIdx.x * 256 + threadIdx.x;
    if (idx >= N * DMODEL) return;
    int n = idx / DMODEL, k = idx % DMODEL;
    Wt[idx] = __float2bfloat16(W[(size_t)k * N + n]);
}

__global__ void wtrans2_kernel(const float* __restrict__ Woff, const float* __restrict__ Wattn,
                               __nv_bfloat16* __restrict__ Wt) {
    int idx = blockIdx.x * 256 + threadIdx.x;
    if (idx >= NCOMB_PAD * DMODEL) return;
    int n = idx / DMODEL, k = idx % DMODEL;
    float v = 0.f;
    if (n < NOFF) v = Woff[(size_t)k * NOFF + n];
    else if (n < NCOMB) v = Wattn[(size_t)k * NATT + (n - NOFF)];
    Wt[idx] = __float2bfloat16(v);
}

// ---------------------------------------------------------------------------
// LayerNorm over last dim (768), one block per row, write bf16
// ---------------------------------------------------------------------------
__global__ void __launch_bounds__(256) ln_kernel(
    const float* __restrict__ x, const float* __restrict__ g,
    const float* __restrict__ b, __nv_bfloat16* __restrict__ out)
{
    int row = blockIdx.x;
    const float* xr = x + (size_t)row * DMODEL;
    float v[3];
    float s = 0.f, s2 = 0.f;
#pragma unroll
    for (int i = 0; i < 3; i++) {
        v[i] = xr[threadIdx.x + i * 256];
        s += v[i];
        s2 += v[i] * v[i];
    }
    __shared__ float red0[32], red1[32];
#pragma unroll
    for (int o = 16; o > 0; o >>= 1) {
        s  += __shfl_xor_sync(0xFFFFFFFFu, s,  o);
        s2 += __shfl_xor_sync(0xFFFFFFFFu, s2, o);
    }
    int wid = threadIdx.x >> 5, lid = threadIdx.x & 31;
    if (lid == 0) { red0[wid] = s; red1[wid] = s2; }
    __syncthreads();
    if (wid == 0) {
        s  = (lid < 8) ? red0[lid] : 0.f;
        s2 = (lid < 8) ? red1[lid] : 0.f;
#pragma unroll
        for (int o = 4; o > 0; o >>= 1) {
            s  += __shfl_xor_sync(0xFFFFFFFFu, s,  o);
            s2 += __shfl_xor_sync(0xFFFFFFFFu, s2, o);
        }
        if (lid == 0) { red0[0] = s; red1[0] = s2; }
    }
    __syncthreads();
    float mean = red0[0] * (1.f / DMODEL);
    float var  = red1[0] * (1.f / DMODEL) - mean * mean;
    float rstd = rsqrtf(var + 1e-6f);
    __nv_bfloat16* o = out + (size_t)row * DMODEL;
#pragma unroll
    for (int i = 0; i < 3; i++) {
        int c = threadIdx.x + i * 256;
        o[c] = __float2bfloat16((v[i] - mean) * rstd * g[c] + b[c]);
    }
}

// ---------------------------------------------------------------------------
// mma.sync bf16 GEMM: C[M, gridDim.y*128] = A[M,768] @ Bt[N,768]^T (+bias)
//   A row-major [M,768] bf16; Bt row-major [N,768] bf16 (".col" B operand).
//   CTA 128x128, 8 warps (2x4), warp tile 64x32, k-chunks of 32,
//   cp.async double buffer, ldmatrix fragments, fp32 accum.
// EPI 0: bf16 C        EPI 1: split off(288)/attn(144) float
// EPI 2: float out = resid + gamma*(acc+bias)
// ---------------------------------------------------------------------------
template <int EPI>
__global__ void __launch_bounds__(256) gemm_mma_kernel(
    const __nv_bfloat16* __restrict__ A, const __nv_bfloat16* __restrict__ Bt,
    int M, const float* __restrict__ bias0, const float* __restrict__ bias1,
    void* __restrict__ out0, void* __restrict__ out1,
    const float* __restrict__ resid, const float* __restrict__ gamma)
{
    __shared__ __nv_bfloat16 sA[2][BM][APAD];
    __shared__ __nv_bfloat16 sB[2][BN][APAD];

    const int tid  = threadIdx.x;
    const int wid  = tid >> 5;
    const int lane = tid & 31;
    const int wm   = wid >> 2;        // 0..1
    const int wn   = wid & 3;         // 0..3
    const int m0   = blockIdx.x * BM;
    const int n0   = blockIdx.y * BN;

    const uint32_t sAaddr = smem_u32(&sA[0][0][0]);
    const uint32_t sBaddr = smem_u32(&sB[0][0][0]);
    const uint32_t BUFB   = BM * APAD * 2;   // bytes per buffer

    // per-thread cp.async coords: 512 16B-chunks per tile, 2 per thread
    const int c0row = tid >> 2, c0cg = tid & 3;          // chunk tid
    const int c1row = (tid + 256) >> 2, c1cg = tid & 3;  // chunk tid+256

    float acc[4][4][4];
#pragma unroll
    for (int mi = 0; mi < 4; mi++)
#pragma unroll
        for (int ni = 0; ni < 4; ni++)
#pragma unroll
            for (int r = 0; r < 4; r++) acc[mi][ni][r] = 0.f;

    auto load_tile = [&](int kt, int s) {
        const int k0 = kt * BK;
        {
            int ar = m0 + c0row; if (ar >= M) ar = M - 1;
            CP_ASYNC16(sAaddr + s * BUFB + c0row * (APAD * 2) + c0cg * 16,
                       A + (size_t)ar * DMODEL + k0 + c0cg * 8);
            CP_ASYNC16(sBaddr + s * BUFB + c0row * (APAD * 2) + c0cg * 16,
                       Bt + (size_t)(n0 + c0row) * DMODEL + k0 + c0cg * 8);
        }
        {
            int ar = m0 + c1row; if (ar >= M) ar = M - 1;
            CP_ASYNC16(sAaddr + s * BUFB + c1row * (APAD * 2) + c1cg * 16,
                       A + (size_t)ar * DMODEL + k0 + c1cg * 8);
            CP_ASYNC16(sBaddr + s * BUFB + c1row * (APAD * 2) + c1cg * 16,
                       Bt + (size_t)(n0 + c1row) * DMODEL + k0 + c1cg * 8);
        }
    };

    // ldmatrix lane addressing
    const int alr = lane & 15;            // A row within 16
    const int alc = lane >> 4;            // A col half (0/1 -> +8 elems)
    const int blr = lane & 7;             // B row within 8
    const int blc = (lane >> 3) & 1;      // B k half

    load_tile(0, 0);
    CP_COMMIT();

#pragma unroll 1
    for (int kt = 0; kt < KTILES; kt++) {
        const int s = kt & 1;
        if (kt + 1 < KTILES) load_tile(kt + 1, (kt + 1) & 1);
        CP_COMMIT();
        CP_WAIT1();
        __syncthreads();

        const uint32_t aBase = sAaddr + s * BUFB + (wm * 64 + alr) * (APAD * 2) + alc * 16;
        const uint32_t bBase = sBaddr + s * BUFB + (wn * 32 + blr) * (APAD * 2) + blc * 16;
#pragma unroll
        for (int ks = 0; ks < 2; ks++) {
            uint32_t af[4][4], bf[4][2];
#pragma unroll
            for (int mi = 0; mi < 4; mi++)
                LDSM_X4(af[mi], aBase + mi * 16 * (APAD * 2) + ks * 32);
#pragma unroll
            for (int ni = 0; ni < 4; ni++)
                LDSM_X2(bf[ni], bBase + ni * 8 * (APAD * 2) + ks * 32);
#pragma unroll
            for (int mi = 0; mi < 4; mi++)
#pragma unroll
                for (int ni = 0; ni < 4; ni++)
                    MMA_16816(acc[mi][ni], af[mi], bf[ni]);
        }
        __syncthreads();
    }

    // ---------------- epilogue ----------------
    const int groupID = lane >> 2, tig = lane & 3;
#pragma unroll
    for (int mi = 0; mi < 4; mi++) {
        const int r0 = m0 + wm * 64 + mi * 16 + groupID;
        const int r1 = r0 + 8;
#pragma unroll
        for (int ni = 0; ni < 4; ni++) {
            const int cb = n0 + wn * 32 + ni * 8 + tig * 2;
            const float* a4 = acc[mi][ni];
            if (EPI == 0) {
                __nv_bfloat16* o = (__nv_bfloat16*)out0;
                float b0v = bias0[cb], b1v = bias0[cb + 1];
                if (r0 < M) {
                    __nv_bfloat162 v;
                    v.x = __float2bfloat16(a4[0] + b0v);
                    v.y = __float2bfloat16(a4[1] + b1v);
                    *reinterpret_cast<__nv_bfloat162*>(o + (size_t)r0 * DMODEL + cb) = v;
                }
                if (r1 < M) {
                    __nv_bfloat162 v;
                    v.x = __float2bfloat16(a4[2] + b0v);
                    v.y = __float2bfloat16(a4[3] + b1v);
                    *reinterpret_cast<__nv_bfloat162*>(o + (size_t)r1 * DMODEL + cb) = v;
                }
            } else if (EPI == 1) {
                float* o0 = (float*)out0;
                float* o1 = (float*)out1;
#pragma unroll
                for (int e = 0; e < 2; e++) {
                    int n = cb + e;
                    float v0 = a4[e], v1 = a4[2 + e];
                    if (n < NOFF) {
                        o0[(size_t)r0 * NOFF + n] = v0 + bias0[n];
                        o0[(size_t)r1 * NOFF + n] = v1 + bias0[n];
                    } else if (n < NCOMB) {
                        o1[(size_t)r0 * NATT + (n - NOFF)] = v0 + bias1[n - NOFF];
                        o1[(size_t)r1 * NATT + (n - NOFF)] = v1 + bias1[n - NOFF];
                    }
                }
            } else {
                float* o = (float*)out0;
#pragma unroll
                for (int e = 0; e < 2; e++) {
                    int n = cb + e;
                    o[(size_t)r0 * DMODEL + n] = resid[(size_t)r0 * DMODEL + n] +
                                                 gamma[n] * (a4[e] + bias0[n]);
                    o[(size_t)r1 * DMODEL + n] = resid[(size_t)r1 * DMODEL + n] +
                                                 gamma[n] * (a4[2 + e] + bias0[n]);
                }
            }
        }
    }
}

// ---------------------------------------------------------------------------
// Softmax over groups of 12 (NL*NP), in place
// ---------------------------------------------------------------------------
__global__ void softmax12_kernel(float* __restrict__ aw, int ngroups) {
    int i = blockIdx.x * 256 + threadIdx.x;
    if (i >= ngroups) return;
    float* p = aw + (size_t)i * 12;
    float v[12];
    float m = -1e30f;
#pragma unroll
    for (int j = 0; j < 12; j++) { v[j] = p[j]; m = fmaxf(m, v[j]); }
    float s = 0.f;
#pragma unroll
    for (int j = 0; j < 12; j++) { v[j] = __expf(v[j] - m); s += v[j]; }
    float inv = 1.f / s;
#pragma unroll
    for (int j = 0; j < 12; j++) p[j] = v[j] * inv;
}

// ---------------------------------------------------------------------------
// Deformable sampling: one warp per (b, q, h). Each lane owns 2 of 64 dims.
// ---------------------------------------------------------------------------
__global__ void __launch_bounds__(256) sample_kernel(
    const float* __restrict__ off, const float* __restrict__ aw,
    const __nv_bfloat16* __restrict__ val, __nv_bfloat16* __restrict__ sam)
{
    constexpr int lvl_h[3] = {112, 56, 28};
    constexpr int lvl_w[3] = {112, 56, 28};
    constexpr int lvl_s[3] = {0, 12544, 15680};

    int warp = (blockIdx.x * blockDim.x + threadIdx.x) >> 5;
    int lane = threadIdx.x & 31;
    if (warp >= BATCH * LQ * NHEAD) return;
    int h  = warp % NHEAD;
    int bq = warp / NHEAD;
    int q  = bq % LQ;
    int b  = bq / LQ;

    float rx = ((q & 63) + 0.5f) * (1.f / 64.f);
    float ry = ((q >> 6) + 0.5f) * (1.f / 64.f);

    const float* offp = off + (size_t)warp * (NLVL * NPT * 2);
    const float* awp  = aw  + (size_t)warp * (NLVL * NPT);

    float acc0 = 0.f, acc1 = 0.f;

#pragma unroll
    for (int l = 0; l < NLVL; l++) {
        const int h_ = lvl_h[l], w_ = lvl_w[l], st = lvl_s[l];
        const float invw = 1.f / (float)w_, invh = 1.f / (float)h_;
#pragma unroll
        for (int p = 0; p < NPT; p++) {
            float ox = offp[(l * NPT + p) * 2];
            float oy = offp[(l * NPT + p) * 2 + 1];
            float a  = awp[l * NPT + p];
            float x = (rx + ox * invw) * (float)w_ - 0.5f;
            float y = (ry + oy * invh) * (float)h_ - 0.5f;
            float x0f = floorf(x), y0f = floorf(y);
            float wx = x - x0f, wy = y - y0f;
            int x0 = (int)x0f, y0 = (int)y0f;
            float w00 = (1.f - wx) * (1.f - wy) * a;
            float w01 = wx * (1.f - wy) * a;
            float w10 = (1.f - wx) * wy * a;
            float w11 = wx * wy * a;

            const int xs[4] = {x0, x0 + 1, x0, x0 + 1};
            const int ys[4] = {y0, y0, y0 + 1, y0 + 1};
            const float ws[4] = {w00, w01, w10, w11};
#pragma unroll
            for (int c = 0; c < 4; c++) {
                int xi = xs[c], yi = ys[c];
                if (xi >= 0 && xi < w_ && yi >= 0 && yi < h_) {
                    size_t base = (((size_t)b * LIN + st + (size_t)yi * w_ + xi) * NHEAD + h)
                                  * HDIM + lane * 2;
                    __nv_bfloat162 v2 = *reinterpret_cast<const __nv_bfloat162*>(val + base);
                    float2 f = __bfloat1622float2(v2);
                    acc0 += ws[c] * f.x;
                    acc1 += ws[c] * f.y;
                }
            }
        }
    }

    size_t so = (size_t)(b * LQ + q) * DMODEL + h * HDIM + lane * 2;
    __nv_bfloat162 r;
    r.x = __float2bfloat16(acc0);
    r.y = __float2bfloat16(acc1);
    *reinterpret_cast<__nv_bfloat162*>(sam + so) = r;
}

// ---------------------------------------------------------------------------
// Launch
// ---------------------------------------------------------------------------
extern "C" void kernel_launch(void* const* d_in, const int* in_sizes, int n_in,
                              void* d_out, int out_size)
{
    const float* query  = (const float*)d_in[0];
    const float* feat   = (const float*)d_in[1];
    const float* ln_q_g = (const float*)d_in[2];
    const float* ln_q_b = (const float*)d_in[3];
    const float* ln_f_g = (const float*)d_in[4];
    const float* ln_f_b = (const float*)d_in[5];
    const float* W_off  = (const float*)d_in[6];
    const float* b_off  = (const float*)d_in[7];
    const float* W_attn = (const float*)d_in[8];
    const float* b_attn = (const float*)d_in[9];
    const float* W_val  = (const float*)d_in[10];
    const float* b_val  = (const float*)d_in[11];
    const float* W_out  = (const float*)d_in[12];
    const float* b_out  = (const float*)d_in[13];
    const float* gamma  = (const float*)d_in[14];
    float* out = (float*)d_out;

    __nv_bfloat16 *p_qln, *p_fln, *p_val, *p_sam, *p_WvalT, *p_WoutT, *p_WcombT;
    float *p_off, *p_aw;
    cudaGetSymbolAddress((void**)&p_qln,   g_qln);
    cudaGetSymbolAddress((void**)&p_fln,   g_fln);
    cudaGetSymbolAddress((void**)&p_val,   g_val);
    cudaGetSymbolAddress((void**)&p_sam,   g_sam);
    cudaGetSymbolAddress((void**)&p_WvalT, g_WvalT);
    cudaGetSymbolAddress((void**)&p_WoutT, g_WoutT);
    cudaGetSymbolAddress((void**)&p_WcombT,g_WcombT);
    cudaGetSymbolAddress((void**)&p_off,   g_off);
    cudaGetSymbolAddress((void**)&p_aw,    g_aw);

    const int Mq = BATCH * LQ;    // 16384
    const int Mf = BATCH * LIN;   // 65856

    // 1. weight transposes -> bf16 [N,K]
    {
        int n = DMODEL * DMODEL;
        wtrans_kernel<<<(n + 255) / 256, 256>>>(W_val, p_WvalT, DMODEL);
        wtrans_kernel<<<(n + 255) / 256, 256>>>(W_out, p_WoutT, DMODEL);
        n = NCOMB_PAD * DMODEL;
        wtrans2_kernel<<<(n + 255) / 256, 256>>>(W_off, W_attn, p_WcombT);
    }

    // 2. LayerNorms
    ln_kernel<<<Mf, 256>>>(feat, ln_f_g, ln_f_b, p_fln);
    ln_kernel<<<Mq, 256>>>(query, ln_q_g, ln_q_b, p_qln);

    // 3. value = ln(feat) @ W_val + b_val   (bf16 out)  [mma.sync]
    gemm_mma_kernel<0><<<dim3((Mf + BM - 1) / BM, DMODEL / BN), 256>>>(
        p_fln, p_WvalT, Mf, b_val, nullptr, p_val, nullptr, nullptr, nullptr);

    // 4+5. fused offsets+attn logits  [mma.sync, split epilogue]
    gemm_mma_kernel<1><<<dim3(Mq / BM, NCOMB_PAD / BN), 256>>>(
        p_qln, p_WcombT, Mq, b_off, b_attn, p_off, p_aw, nullptr, nullptr);

    // 6. softmax over NL*NP=12
    softmax12_kernel<<<(Mq * NHEAD) / 256, 256>>>(p_aw, Mq * NHEAD);

    // 7. deformable sampling -> g_sam (bf16)
    sample_kernel<<<(Mq * NHEAD) / 8, 256>>>(p_off, p_aw, p_val, p_sam);

    // 8. out = query + gamma * (g_sam @ W_out + b_out)  [mma.sync]
    gemm_mma_kernel<2><<<dim3(Mq / BM, DMODEL / BN), 256>>>(
        p_sam, p_WoutT, Mq, b_out, nullptr, out, nullptr, query, gamma);
}

// round 7
// speedup vs baseline: 3.8873x; 1.1463x over previous
#include <cuda_runtime.h>
#include <cuda_bf16.h>
#include <cstdint>

// ---------------------------------------------------------------------------
// Problem constants
// ---------------------------------------------------------------------------
#define BATCH 4
#define DMODEL 768
#define NHEAD 12
#define HDIM 64
#define NLVL 3
#define NPT 4
#define LQ 4096           // 64 x 64 query grid
#define LIN 16464         // 112*112 + 56*56 + 28*28
#define NOFF 288          // NH*NL*NP*2
#define NATT 144          // NH*NL*NP
#define NCOMB 432         // NOFF+NATT
#define NCOMB_PAD 512

// GEMM tiling
#define BM 128
#define BN 128
#define BK 64
#define ROWE 72            // bf16 elements per SMEM row (64 + 8 pad) = 144 B
#define KTILES (DMODEL / BK)   // 12
#define TILEB (BM * ROWE * 2)  // 18432 B per matrix-stage
#define GEMM_SMEM (4 * TILEB)  // 73728 B

// ---------------------------------------------------------------------------
// Scratch (device globals; no runtime allocation allowed)
// ---------------------------------------------------------------------------
__device__ __nv_bfloat16 g_qln[(size_t)BATCH * LQ * DMODEL];
__device__ __nv_bfloat16 g_fln[(size_t)BATCH * LIN * DMODEL];
__device__ __nv_bfloat16 g_val[(size_t)BATCH * LIN * DMODEL];
__device__ float         g_off[(size_t)BATCH * LQ * NOFF];
__device__ float         g_aw [(size_t)BATCH * LQ * NATT];
__device__ __nv_bfloat16 g_sam[(size_t)BATCH * LQ * DMODEL];
__device__ __nv_bfloat16 g_WvalT[DMODEL * DMODEL];        // [n][k]
__device__ __nv_bfloat16 g_WoutT[DMODEL * DMODEL];        // [n][k]
__device__ __nv_bfloat16 g_WcombT[NCOMB_PAD * DMODEL];    // [n][k], rows >=432 zero

// ---------------------------------------------------------------------------
// helpers
// ---------------------------------------------------------------------------
__device__ __forceinline__ uint32_t smem_u32(const void* p) {
    uint32_t a;
    asm("{ .reg .u64 t; cvta.to.shared.u64 t, %1; cvt.u32.u64 %0, t; }" : "=r"(a) : "l"(p));
    return a;
}

#define CP_ASYNC16(sp, gp) \
    asm volatile("cp.async.cg.shared.global [%0], [%1], 16;" :: "r"(sp), "l"(gp) : "memory")
#define CP_COMMIT() asm volatile("cp.async.commit_group;" ::: "memory")
#define CP_WAIT1()  asm volatile("cp.async.wait_group 1;" ::: "memory")

#define LDSM_X4(r, addr)                                                      \
    asm volatile("ldmatrix.sync.aligned.m8n8.x4.shared.b16 {%0,%1,%2,%3}, [%4];" \
        : "=r"((r)[0]), "=r"((r)[1]), "=r"((r)[2]), "=r"((r)[3]) : "r"(addr))
#define LDSM_X2(r, addr)                                                      \
    asm volatile("ldmatrix.sync.aligned.m8n8.x2.shared.b16 {%0,%1}, [%2];"    \
        : "=r"((r)[0]), "=r"((r)[1]) : "r"(addr))

#define MMA_16816(c, a, b)                                                    \
    asm volatile("mma.sync.aligned.m16n8k16.row.col.f32.bf16.bf16.f32 "       \
        "{%0,%1,%2,%3}, {%4,%5,%6,%7}, {%8,%9}, {%0,%1,%2,%3};"               \
        : "+f"((c)[0]), "+f"((c)[1]), "+f"((c)[2]), "+f"((c)[3])              \
        : "r"((a)[0]), "r"((a)[1]), "r"((a)[2]), "r"((a)[3]),                 \
          "r"((b)[0]), "r"((b)[1]))

// ---------------------------------------------------------------------------
// Tiled transpose fp32 [K,N] -> bf16 [N,K]  (32x32 smem tiles, coalesced)
// ---------------------------------------------------------------------------
__global__ void __launch_bounds__(256) wtransT_kernel(
    const float* __restrict__ W, __nv_bfloat16* __restrict__ Wt, int K, int N)
{
    __shared__ float t[32][33];
    const int kb = blockIdx.x * 32, nb = blockIdx.y * 32;
    const int tx = threadIdx.x & 31, ty = threadIdx.x >> 5;   // 32 x 8
#pragma unroll
    for (int i = 0; i < 32; i += 8) {
        int k = kb + ty + i, n = nb + tx;
        float v = (k < K && n < N) ? W[(size_t)k * N + n] : 0.f;
        t[ty + i][tx] = v;
    }
    __syncthreads();
#pragma unroll
    for (int i = 0; i < 32; i += 8) {
        int n = nb + ty + i, k = kb + tx;
        if (n < N && k < K)
            Wt[(size_t)n * K + k] = __float2bfloat16(t[tx][ty + i]);
    }
}

// combined off+attn transpose into padded [NCOMB_PAD, K]; rows >= NCOMB get 0
__global__ void __launch_bounds__(256) wtransC_kernel(
    const float* __restrict__ Woff, const float* __restrict__ Wattn,
    __nv_bfloat16* __restrict__ Wt)
{
    __shared__ float t[32][33];
    const int kb = blockIdx.x * 32, nb = blockIdx.y * 32;
    const int tx = threadIdx.x & 31, ty = threadIdx.x >> 5;
#pragma unroll
    for (int i = 0; i < 32; i += 8) {
        int k = kb + ty + i, n = nb + tx;
        float v = 0.f;
        if (k < DMODEL) {
            if (n < NOFF) v = Woff[(size_t)k * NOFF + n];
            else if (n < NCOMB) v = Wattn[(size_t)k * NATT + (n - NOFF)];
        }
        t[ty + i][tx] = v;
    }
    __syncthreads();
#pragma unroll
    for (int i = 0; i < 32; i += 8) {
        int n = nb + ty + i, k = kb + tx;
        if (n < NCOMB_PAD && k < DMODEL)
            Wt[(size_t)n * DMODEL + k] = __float2bfloat16(t[tx][ty + i]);
    }
}

// ---------------------------------------------------------------------------
// LayerNorm: one warp per row (768), float4 loads, shuffle-only reduction
// ---------------------------------------------------------------------------
__global__ void __launch_bounds__(256) ln_kernel(
    const float* __restrict__ x, const float* __restrict__ g,
    const float* __restrict__ b, __nv_bfloat16* __restrict__ out, int nrows)
{
    const int row = blockIdx.x * 8 + (threadIdx.x >> 5);
    const int lane = threadIdx.x & 31;
    if (row >= nrows) return;
    const float4* xr = reinterpret_cast<const float4*>(x + (size_t)row * DMODEL);
    float4 v[6];
    float s = 0.f, s2 = 0.f;
#pragma unroll
    for (int i = 0; i < 6; i++) {
        v[i] = xr[i * 32 + lane];
        s  += v[i].x + v[i].y + v[i].z + v[i].w;
        s2 += v[i].x * v[i].x + v[i].y * v[i].y + v[i].z * v[i].z + v[i].w * v[i].w;
    }
#pragma unroll
    for (int o = 16; o > 0; o >>= 1) {
        s  += __shfl_xor_sync(0xFFFFFFFFu, s,  o);
        s2 += __shfl_xor_sync(0xFFFFFFFFu, s2, o);
    }
    const float mean = s * (1.f / DMODEL);
    const float var  = s2 * (1.f / DMODEL) - mean * mean;
    const float rstd = rsqrtf(var + 1e-6f);
    const float4* gp = reinterpret_cast<const float4*>(g);
    const float4* bp = reinterpret_cast<const float4*>(b);
    uint2* o = reinterpret_cast<uint2*>(out + (size_t)row * DMODEL);
#pragma unroll
    for (int i = 0; i < 6; i++) {
        float4 gv = gp[i * 32 + lane];
        float4 bv = bp[i * 32 + lane];
        __nv_bfloat162 p0, p1;
        p0.x = __float2bfloat16((v[i].x - mean) * rstd * gv.x + bv.x);
        p0.y = __float2bfloat16((v[i].y - mean) * rstd * gv.y + bv.y);
        p1.x = __float2bfloat16((v[i].z - mean) * rstd * gv.z + bv.z);
        p1.y = __float2bfloat16((v[i].w - mean) * rstd * gv.w + bv.w);
        uint2 w;
        w.x = *reinterpret_cast<uint32_t*>(&p0);
        w.y = *reinterpret_cast<uint32_t*>(&p1);
        o[i * 32 + lane] = w;
    }
}

// ---------------------------------------------------------------------------
// mma.sync bf16 GEMM: C[M, gridDim.y*128] = A[M,768] @ Bt[N,768]^T (+bias)
//   CTA 128x128, 8 warps (2x4), warp tile 64x32, k-chunks of 64,
//   cp.async double buffer (dynamic smem), ldmatrix fragments, fp32 accum.
// EPI 0: bf16 C        EPI 1: split off(288)/attn(144) float
// EPI 2: float out = resid + gamma*(acc+bias)
// ---------------------------------------------------------------------------
template <int EPI>
__global__ void __launch_bounds__(256) gemm_mma_kernel(
    const __nv_bfloat16* __restrict__ A, const __nv_bfloat16* __restrict__ Bt,
    int M, const float* __restrict__ bias0, const float* __restrict__ bias1,
    void* __restrict__ out0, void* __restrict__ out1,
    const float* __restrict__ resid, const float* __restrict__ gamma)
{
    extern __shared__ char smem[];
    const uint32_t sbase = smem_u32(smem);

    const int tid  = threadIdx.x;
    const int wid  = tid >> 5;
    const int lane = tid & 31;
    const int wm   = wid >> 2;        // 0..1
    const int wn   = wid & 3;         // 0..3
    const int m0   = blockIdx.x * BM;
    const int n0   = blockIdx.y * BN;

    // layout: [A0][B0][A1][B1], each TILEB bytes
    const uint32_t aOff[2] = {sbase, sbase + 2 * TILEB};
    const uint32_t bOff[2] = {sbase + TILEB, sbase + 3 * TILEB};

    float acc[4][4][4];
#pragma unroll
    for (int mi = 0; mi < 4; mi++)
#pragma unroll
        for (int ni = 0; ni < 4; ni++)
#pragma unroll
            for (int r = 0; r < 4; r++) acc[mi][ni][r] = 0.f;

    // 1024 16B-chunks per matrix-tile, 4 per thread
    auto load_tile = [&](int kt, int s) {
        const int k0 = kt * BK;
#pragma unroll
        for (int t = 0; t < 4; t++) {
            int c = t * 256 + tid;
            int row = c >> 3, col = c & 7;
            int ar = m0 + row; if (ar >= M) ar = M - 1;
            CP_ASYNC16(aOff[s] + row * (ROWE * 2) + col * 16,
                       A + (size_t)ar * DMODEL + k0 + col * 8);
            CP_ASYNC16(bOff[s] + row * (ROWE * 2) + col * 16,
                       Bt + (size_t)(n0 + row) * DMODEL + k0 + col * 8);
        }
    };

    // ldmatrix lane addressing
    const int alr = lane & 15;            // A row within 16
    const int alc = lane >> 4;            // A col half (+8 elems)
    const int blr = lane & 7;             // B row within 8
    const int blc = (lane >> 3) & 1;      // B k half

    load_tile(0, 0);
    CP_COMMIT();

#pragma unroll 1
    for (int kt = 0; kt < KTILES; kt++) {
        const int s = kt & 1;
        if (kt + 1 < KTILES) load_tile(kt + 1, (kt + 1) & 1);
        CP_COMMIT();
        CP_WAIT1();
        __syncthreads();

        const uint32_t aBase = aOff[s] + (wm * 64 + alr) * (ROWE * 2) + alc * 16;
        const uint32_t bBase = bOff[s] + (wn * 32 + blr) * (ROWE * 2) + blc * 16;
#pragma unroll
        for (int ks = 0; ks < 4; ks++) {
            uint32_t af[4][4], bf[4][2];
#pragma unroll
            for (int mi = 0; mi < 4; mi++)
                LDSM_X4(af[mi], aBase + mi * 16 * (ROWE * 2) + ks * 32);
#pragma unroll
            for (int ni = 0; ni < 4; ni++)
                LDSM_X2(bf[ni], bBase + ni * 8 * (ROWE * 2) + ks * 32);
#pragma unroll
            for (int mi = 0; mi < 4; mi++)
#pragma unroll
                for (int ni = 0; ni < 4; ni++)
                    MMA_16816(acc[mi][ni], af[mi], bf[ni]);
        }
        __syncthreads();
    }

    // ---------------- epilogue ----------------
    const int groupID = lane >> 2, tig = lane & 3;
#pragma unroll
    for (int mi = 0; mi < 4; mi++) {
        const int r0 = m0 + wm * 64 + mi * 16 + groupID;
        const int r1 = r0 + 8;
#pragma unroll
        for (int ni = 0; ni < 4; ni++) {
            const int cb = n0 + wn * 32 + ni * 8 + tig * 2;
            const float* a4 = acc[mi][ni];
            if (EPI == 0) {
                __nv_bfloat16* o = (__nv_bfloat16*)out0;
                float b0v = bias0[cb], b1v = bias0[cb + 1];
                if (r0 < M) {
                    __nv_bfloat162 v;
                    v.x = __float2bfloat16(a4[0] + b0v);
                    v.y = __float2bfloat16(a4[1] + b1v);
                    *reinterpret_cast<__nv_bfloat162*>(o + (size_t)r0 * DMODEL + cb) = v;
                }
                if (r1 < M) {
                    __nv_bfloat162 v;
                    v.x = __float2bfloat16(a4[2] + b0v);
                    v.y = __float2bfloat16(a4[3] + b1v);
                    *reinterpret_cast<__nv_bfloat162*>(o + (size_t)r1 * DMODEL + cb) = v;
                }
            } else if (EPI == 1) {
                float* o0 = (float*)out0;
                float* o1 = (float*)out1;
#pragma unroll
                for (int e = 0; e < 2; e++) {
                    int n = cb + e;
                    float v0 = a4[e], v1 = a4[2 + e];
                    if (n < NOFF) {
                        o0[(size_t)r0 * NOFF + n] = v0 + bias0[n];
                        o0[(size_t)r1 * NOFF + n] = v1 + bias0[n];
                    } else if (n < NCOMB) {
                        o1[(size_t)r0 * NATT + (n - NOFF)] = v0 + bias1[n - NOFF];
                        o1[(size_t)r1 * NATT + (n - NOFF)] = v1 + bias1[n - NOFF];
                    }
                }
            } else {
                float* o = (float*)out0;
#pragma unroll
                for (int e = 0; e < 2; e++) {
                    int n = cb + e;
                    o[(size_t)r0 * DMODEL + n] = resid[(size_t)r0 * DMODEL + n] +
                                                 gamma[n] * (a4[e] + bias0[n]);
                    o[(size_t)r1 * DMODEL + n] = resid[(size_t)r1 * DMODEL + n] +
                                                 gamma[n] * (a4[2 + e] + bias0[n]);
                }
            }
        }
    }
}

// ---------------------------------------------------------------------------
// Deformable sampling with fused softmax: one warp per (b, q, h).
// ---------------------------------------------------------------------------
__global__ void __launch_bounds__(256) sample_kernel(
    const float* __restrict__ off, const float* __restrict__ aw,
    const __nv_bfloat16* __restrict__ val, __nv_bfloat16* __restrict__ sam)
{
    constexpr int lvl_h[3] = {112, 56, 28};
    constexpr int lvl_w[3] = {112, 56, 28};
    constexpr int lvl_s[3] = {0, 12544, 15680};

    int warp = (blockIdx.x * blockDim.x + threadIdx.x) >> 5;
    int lane = threadIdx.x & 31;
    if (warp >= BATCH * LQ * NHEAD) return;
    int h  = warp % NHEAD;
    int bq = warp / NHEAD;
    int q  = bq % LQ;
    int b  = bq / LQ;

    float rx = ((q & 63) + 0.5f) * (1.f / 64.f);
    float ry = ((q >> 6) + 0.5f) * (1.f / 64.f);

    const float* offp = off + (size_t)warp * (NLVL * NPT * 2);
    const float* awp  = aw  + (size_t)warp * (NLVL * NPT);

    // softmax over 12 logits (uniform across warp; broadcast loads)
    float lg[12];
    float mx = -1e30f;
#pragma unroll
    for (int j = 0; j < 12; j++) { lg[j] = awp[j]; mx = fmaxf(mx, lg[j]); }
    float ssum = 0.f;
#pragma unroll
    for (int j = 0; j < 12; j++) { lg[j] = __expf(lg[j] - mx); ssum += lg[j]; }
    const float sinv = 1.f / ssum;

    float acc0 = 0.f, acc1 = 0.f;

#pragma unroll
    for (int l = 0; l < NLVL; l++) {
        const int h_ = lvl_h[l], w_ = lvl_w[l], st = lvl_s[l];
        const float invw = 1.f / (float)w_, invh = 1.f / (float)h_;
#pragma unroll
        for (int p = 0; p < NPT; p++) {
            float ox = offp[(l * NPT + p) * 2];
            float oy = offp[(l * NPT + p) * 2 + 1];
            float a  = lg[l * NPT + p] * sinv;
            float x = (rx + ox * invw) * (float)w_ - 0.5f;
            float y = (ry + oy * invh) * (float)h_ - 0.5f;
            float x0f = floorf(x), y0f = floorf(y);
            float wx = x - x0f, wy = y - y0f;
            int x0 = (int)x0f, y0 = (int)y0f;
            float w00 = (1.f - wx) * (1.f - wy) * a;
            float w01 = wx * (1.f - wy) * a;
            float w10 = (1.f - wx) * wy * a;
            float w11 = wx * wy * a;

            const int xs[4] = {x0, x0 + 1, x0, x0 + 1};
            const int ys[4] = {y0, y0, y0 + 1, y0 + 1};
            const float ws[4] = {w00, w01, w10, w11};
#pragma unroll
            for (int c = 0; c < 4; c++) {
                int xi = xs[c], yi = ys[c];
                if (xi >= 0 && xi < w_ && yi >= 0 && yi < h_) {
                    size_t base = (((size_t)b * LIN + st + (size_t)yi * w_ + xi) * NHEAD + h)
                                  * HDIM + lane * 2;
                    __nv_bfloat162 v2 = *reinterpret_cast<const __nv_bfloat162*>(val + base);
                    float2 f = __bfloat1622float2(v2);
                    acc0 += ws[c] * f.x;
                    acc1 += ws[c] * f.y;
                }
            }
        }
    }

    size_t so = (size_t)(b * LQ + q) * DMODEL + h * HDIM + lane * 2;
    __nv_bfloat162 r;
    r.x = __float2bfloat16(acc0);
    r.y = __float2bfloat16(acc1);
    *reinterpret_cast<__nv_bfloat162*>(sam + so) = r;
}

// ---------------------------------------------------------------------------
// Launch
// ---------------------------------------------------------------------------
extern "C" void kernel_launch(void* const* d_in, const int* in_sizes, int n_in,
                              void* d_out, int out_size)
{
    const float* query  = (const float*)d_in[0];
    const float* feat   = (const float*)d_in[1];
    const float* ln_q_g = (const float*)d_in[2];
    const float* ln_q_b = (const float*)d_in[3];
    const float* ln_f_g = (const float*)d_in[4];
    const float* ln_f_b = (const float*)d_in[5];
    const float* W_off  = (const float*)d_in[6];
    const float* b_off  = (const float*)d_in[7];
    const float* W_attn = (const float*)d_in[8];
    const float* b_attn = (const float*)d_in[9];
    const float* W_val  = (const float*)d_in[10];
    const float* b_val  = (const float*)d_in[11];
    const float* W_out  = (const float*)d_in[12];
    const float* b_out  = (const float*)d_in[13];
    const float* gamma  = (const float*)d_in[14];
    float* out = (float*)d_out;

    __nv_bfloat16 *p_qln, *p_fln, *p_val, *p_sam, *p_WvalT, *p_WoutT, *p_WcombT;
    float *p_off, *p_aw;
    cudaGetSymbolAddress((void**)&p_qln,   g_qln);
    cudaGetSymbolAddress((void**)&p_fln,   g_fln);
    cudaGetSymbolAddress((void**)&p_val,   g_val);
    cudaGetSymbolAddress((void**)&p_sam,   g_sam);
    cudaGetSymbolAddress((void**)&p_WvalT, g_WvalT);
    cudaGetSymbolAddress((void**)&p_WoutT, g_WoutT);
    cudaGetSymbolAddress((void**)&p_WcombT,g_WcombT);
    cudaGetSymbolAddress((void**)&p_off,   g_off);
    cudaGetSymbolAddress((void**)&p_aw,    g_aw);

    // dynamic-smem opt-in (idempotent; not a stream op, capture-safe)
    cudaFuncSetAttribute(gemm_mma_kernel<0>, cudaFuncAttributeMaxDynamicSharedMemorySize, GEMM_SMEM);
    cudaFuncSetAttribute(gemm_mma_kernel<1>, cudaFuncAttributeMaxDynamicSharedMemorySize, GEMM_SMEM);
    cudaFuncSetAttribute(gemm_mma_kernel<2>, cudaFuncAttributeMaxDynamicSharedMemorySize, GEMM_SMEM);

    const int Mq = BATCH * LQ;    // 16384
    const int Mf = BATCH * LIN;   // 65856

    // 1. weight transposes -> bf16 [N,K] (tiled, coalesced)
    wtransT_kernel<<<dim3(DMODEL / 32, DMODEL / 32), 256>>>(W_val, p_WvalT, DMODEL, DMODEL);
    wtransT_kernel<<<dim3(DMODEL / 32, DMODEL / 32), 256>>>(W_out, p_WoutT, DMODEL, DMODEL);
    wtransC_kernel<<<dim3(DMODEL / 32, NCOMB_PAD / 32), 256>>>(W_off, W_attn, p_WcombT);

    // 2. LayerNorms (warp per row)
    ln_kernel<<<(Mf + 7) / 8, 256>>>(feat, ln_f_g, ln_f_b, p_fln, Mf);
    ln_kernel<<<(Mq + 7) / 8, 256>>>(query, ln_q_g, ln_q_b, p_qln, Mq);

    // 3. value = ln(feat) @ W_val + b_val   (bf16 out)
    gemm_mma_kernel<0><<<dim3((Mf + BM - 1) / BM, DMODEL / BN), 256, GEMM_SMEM>>>(
        p_fln, p_WvalT, Mf, b_val, nullptr, p_val, nullptr, nullptr, nullptr);

    // 4+5. fused offsets+attn logits (split epilogue; softmax deferred to sampling)
    gemm_mma_kernel<1><<<dim3(Mq / BM, NCOMB_PAD / BN), 256, GEMM_SMEM>>>(
        p_qln, p_WcombT, Mq, b_off, b_attn, p_off, p_aw, nullptr, nullptr);

    // 6+7. deformable sampling with fused softmax -> g_sam (bf16)
    sample_kernel<<<(Mq * NHEAD) / 8, 256>>>(p_off, p_aw, p_val, p_sam);

    // 8. out = query + gamma * (g_sam @ W_out + b_out)
    gemm_mma_kernel<2><<<dim3(Mq / BM, DMODEL / BN), 256, GEMM_SMEM>>>(
        p_sam, p_WoutT, Mq, b_out, nullptr, out, nullptr, query, gamma);
}